// round 6
// baseline (speedup 1.0000x reference)
#include <cuda_runtime.h>
#include <cstdint>

// Deriv2Matern52: out[i,a,j,b] = c^2 * ( (a==b)*A(i,j)*inv_l2[a] - 5*fr(i,j)*D[i,j,a]*D[i,j,b] )
//
// TMA bulk-store version: stores bypass the L1tex store path entirely.
// Per CTA (i, j-tile of 256): for each a, stage the contiguous 8KB slice
// out[i, a, j0:j0+256, 0:8] in smem (double-buffered), then one thread issues
// cp.async.bulk.global.shared::cta (SMEM -> L2 via TMA engine).
// 2 threads per pair; STS.128 at t*16B is bank-conflict-free.

#define D_DIM 8
#define JT 256           // j-tile per block
#define NTHREADS 512     // 2 threads per pair
#define SLICE_FLOATS (JT * D_DIM)         // 2048 floats = 8KB per a-slice
#define SLICE_BYTES  (SLICE_FLOATS * 4)
#define SQRT5F 2.2360679774997896f

__device__ __forceinline__ uint32_t smem_u32(const void* p) {
    uint32_t a;
    asm("{ .reg .u64 t; cvta.to.shared.u64 t, %1; cvt.u32.u64 %0, t; }"
        : "=r"(a) : "l"(p));
    return a;
}

__global__ __launch_bounds__(NTHREADS) void deriv2_matern52_kernel(
    const float* __restrict__ X1,   // [n, 8]
    const float* __restrict__ X2,   // [m, 8]
    const float* __restrict__ cptr, // [1]
    const float* __restrict__ lptr, // [8]
    float* __restrict__ out,        // [n, 8, m, 8]
    int m)
{
    __shared__ __align__(128) float buf[2][SLICE_FLOATS];

    const int t    = threadIdx.x;
    const int i    = blockIdx.y;
    const int p    = t >> 1;            // pair index within tile
    const int half = t & 1;
    const int hb   = half * 4;
    const int j    = blockIdx.x * JT + p;

    // ---- per-pair scalars (each thread recomputes; X1 row block-uniform) ----
    float invl2[D_DIM];
#pragma unroll
    for (int a = 0; a < D_DIM; a++) {
        float lv = __ldg(lptr + a);
        invl2[a] = 1.0f / (lv * lv);
    }
    float cv = __ldg(cptr);
    float c2 = cv * cv;

    const float4* x1p = reinterpret_cast<const float4*>(X1 + (size_t)i * D_DIM);
    const float4* x2p = reinterpret_cast<const float4*>(X2 + (size_t)j * D_DIM);
    float4 x1a = __ldg(x1p);
    float4 x1b = __ldg(x1p + 1);
    float4 x2a = __ldg(x2p);
    float4 x2b = __ldg(x2p + 1);

    float dx[D_DIM];
    dx[0] = x1a.x - x2a.x; dx[1] = x1a.y - x2a.y;
    dx[2] = x1a.z - x2a.z; dx[3] = x1a.w - x2a.w;
    dx[4] = x1b.x - x2b.x; dx[5] = x1b.y - x2b.y;
    dx[6] = x1b.z - x2b.z; dx[7] = x1b.w - x2b.w;

    float s = 0.0f;
    float Dv[D_DIM];
#pragma unroll
    for (int a = 0; a < D_DIM; a++) {
        Dv[a] = dx[a] * invl2[a];
        s = fmaf(dx[a], Dv[a], s);
    }
    float r   = sqrtf(s);
    float fr  = (5.0f / 3.0f) * __expf(-SQRT5F * r);
    float A   = fr * fmaf(SQRT5F, r, 1.0f);
    float Ac2 = A * c2;
    float m5  = -5.0f * fr * c2;

    float Ad[4];
#pragma unroll
    for (int x = 0; x < 4; x++)
        Ad[x] = Ac2 * invl2[hb + x];

    // smem staging slot for this thread: float4 at (p*8 + hb)
    float4* myslot[2];
    myslot[0] = reinterpret_cast<float4*>(&buf[0][p * D_DIM + hb]);
    myslot[1] = reinterpret_cast<float4*>(&buf[1][p * D_DIM + hb]);
    uint32_t sbase[2];
    sbase[0] = smem_u32(&buf[0][0]);
    sbase[1] = smem_u32(&buf[1][0]);

    // gmem base of (i, a=0, j0, b=0)
    const char* dst0 = reinterpret_cast<const char*>(
        out + (((size_t)i * D_DIM) * (size_t)m + (size_t)(blockIdx.x * JT)) * D_DIM);
    const size_t astride_bytes = (size_t)m * D_DIM * 4;

#pragma unroll
    for (int a = 0; a < D_DIM; a++) {
        const int bsel = a & 1;
        if (a >= 2) {
            // make sure buffer bsel's previous bulk copy has drained
            if (t == 0)
                asm volatile("cp.async.bulk.wait_group 1;" ::: "memory");
            __syncthreads();
        }

        float ta = m5 * Dv[a];
        float o0 = ta * Dv[hb + 0];
        float o1 = ta * Dv[hb + 1];
        float o2 = ta * Dv[hb + 2];
        float o3 = ta * Dv[hb + 3];
        if ((a >> 2) == half) {
            int x = a & 3;
            if      (x == 0) o0 += Ad[0];
            else if (x == 1) o1 += Ad[1];
            else if (x == 2) o2 += Ad[2];
            else             o3 += Ad[3];
        }
        *myslot[bsel] = make_float4(o0, o1, o2, o3);

        __syncthreads();

        if (t == 0) {
            asm volatile("fence.proxy.async.shared::cta;" ::: "memory");
            const void* g = dst0 + (size_t)a * astride_bytes;
            asm volatile(
                "cp.async.bulk.global.shared::cta.bulk_group [%0], [%1], %2;"
                :: "l"(g), "r"(sbase[bsel]), "r"((uint32_t)SLICE_BYTES)
                : "memory");
            asm volatile("cp.async.bulk.commit_group;" ::: "memory");
        }
    }

    if (t == 0)
        asm volatile("cp.async.bulk.wait_group 0;" ::: "memory");
}

extern "C" void kernel_launch(void* const* d_in, const int* in_sizes, int n_in,
                              void* d_out, int out_size)
{
    const float* X1 = (const float*)d_in[0];
    const float* X2 = (const float*)d_in[1];
    const float* c  = (const float*)d_in[2];
    const float* l  = (const float*)d_in[3];
    float* out = (float*)d_out;

    int n = in_sizes[0] / D_DIM;
    int m = in_sizes[1] / D_DIM;

    dim3 grid(m / JT, n);
    deriv2_matern52_kernel<<<grid, NTHREADS>>>(X1, X2, c, l, out, m);
}

// round 7
// speedup vs baseline: 1.1803x; 1.1803x over previous
#include <cuda_runtime.h>

// Deriv2Matern52: out[i,a,j,b] = c^2 * ( (a==b)*A(i,j)*inv_l2[a] - 5*fr(i,j)*D[i,j,a]*D[i,j,b] )
//
// Persistent-grid version of the best (R3) two-phase kernel:
//   - 592 CTAs (148 SMs x occ 4) grid-stride over (i, j-tile) tiles; store
//     streams stay continuous (no wave transitions).
//   - per tile: phase 1 (256 threads) computes per-pair scalars into smem
//     (double-buffered, ONE __syncthreads per tile); phase 2 (512 threads)
//     writes fully coalesced 512B-per-warp STG.128 streaming stores.

#define D_DIM 8
#define JT 256          // j-tile
#define NTHREADS 512    // 2 threads per pair in phase 2
#define SSTRIDE 17      // smem row stride (coprime with 32 banks)
#define SQRT5F 2.2360679774997896f

__global__ __launch_bounds__(NTHREADS) void deriv2_matern52_kernel(
    const float* __restrict__ X1,   // [n, 8]
    const float* __restrict__ X2,   // [m, 8]
    const float* __restrict__ cptr, // [1]
    const float* __restrict__ lptr, // [8]
    float* __restrict__ out,        // [n, 8, m, 8]
    int m, int ntiles, int tiles_per_row)
{
    __shared__ float sp[2][JT * SSTRIDE];
    // sp[s][p*17 + 0..7]  = Dv[a]
    // sp[s][p*17 + 8]     = -5 * fr * c^2
    // sp[s][p*17 + 9..16] = A * c^2 * inv_l2[a]

    const int t = threadIdx.x;

    // uniform constants
    float invl2[D_DIM];
#pragma unroll
    for (int a = 0; a < D_DIM; a++) {
        float lv = __ldg(lptr + a);
        invl2[a] = 1.0f / (lv * lv);
    }
    float cv = __ldg(cptr);
    float c2 = cv * cv;

    const int p    = t >> 1;
    const int half = t & 1;
    const int hb   = half * 4;
    const size_t astride = (size_t)m * D_DIM;

    int sel = 0;
    for (int T = blockIdx.x; T < ntiles; T += gridDim.x, sel ^= 1) {
        const int i  = T / tiles_per_row;
        const int j0 = (T - i * tiles_per_row) * JT;

        // ---------------- phase 1 ----------------
        if (t < JT) {
            const float4* x1p = reinterpret_cast<const float4*>(X1 + (size_t)i * D_DIM);
            const float4* x2p = reinterpret_cast<const float4*>(X2 + (size_t)(j0 + t) * D_DIM);
            float4 x1a = __ldg(x1p);
            float4 x1b = __ldg(x1p + 1);
            float4 x2a = __ldg(x2p);
            float4 x2b = __ldg(x2p + 1);

            float dx[D_DIM];
            dx[0] = x1a.x - x2a.x; dx[1] = x1a.y - x2a.y;
            dx[2] = x1a.z - x2a.z; dx[3] = x1a.w - x2a.w;
            dx[4] = x1b.x - x2b.x; dx[5] = x1b.y - x2b.y;
            dx[6] = x1b.z - x2b.z; dx[7] = x1b.w - x2b.w;

            float s = 0.0f;
            float* row = sp[sel] + t * SSTRIDE;
#pragma unroll
            for (int a = 0; a < D_DIM; a++) {
                float dv = dx[a] * invl2[a];
                row[a] = dv;
                s = fmaf(dx[a], dv, s);
            }
            float r   = sqrtf(s);
            float fr  = (5.0f / 3.0f) * __expf(-SQRT5F * r);
            float A   = fr * fmaf(SQRT5F, r, 1.0f);
            float Ac2 = A * c2;
            row[8] = -5.0f * fr * c2;
#pragma unroll
            for (int a = 0; a < D_DIM; a++)
                row[9 + a] = Ac2 * invl2[a];
        }
        __syncthreads();   // protects this tile's write->read AND the other
                           // buffer's read (2 iterations back) -> one sync/tile

        // ---------------- phase 2 ----------------
        const float* row = sp[sel] + p * SSTRIDE;
        float Dv[D_DIM];
#pragma unroll
        for (int a = 0; a < D_DIM; a++)
            Dv[a] = row[a];
        const float m5 = row[8];
        float Ad[4];
#pragma unroll
        for (int x = 0; x < 4; x++)
            Ad[x] = row[9 + hb + x];

        float* dst = out + ((((size_t)i * D_DIM) * (size_t)m + (size_t)(j0 + p)) * D_DIM) + hb;

#pragma unroll
        for (int a = 0; a < D_DIM; a++) {
            float ta = m5 * Dv[a];
            float o0 = ta * Dv[hb + 0];
            float o1 = ta * Dv[hb + 1];
            float o2 = ta * Dv[hb + 2];
            float o3 = ta * Dv[hb + 3];
            if ((a >> 2) == half) {
                int x = a & 3;
                float add = Ad[x];
                if      (x == 0) o0 += add;
                else if (x == 1) o1 += add;
                else if (x == 2) o2 += add;
                else             o3 += add;
            }
            __stcs(reinterpret_cast<float4*>(dst + (size_t)a * astride),
                   make_float4(o0, o1, o2, o3));
        }
    }
}

extern "C" void kernel_launch(void* const* d_in, const int* in_sizes, int n_in,
                              void* d_out, int out_size)
{
    const float* X1 = (const float*)d_in[0];
    const float* X2 = (const float*)d_in[1];
    const float* c  = (const float*)d_in[2];
    const float* l  = (const float*)d_in[3];
    float* out = (float*)d_out;

    int n = in_sizes[0] / D_DIM;
    int m = in_sizes[1] / D_DIM;

    int tiles_per_row = m / JT;
    int ntiles = n * tiles_per_row;

    int blocks = 148 * 4;               // persistent: one wave, occ 4/SM
    if (blocks > ntiles) blocks = ntiles;

    deriv2_matern52_kernel<<<blocks, NTHREADS>>>(X1, X2, c, l, out,
                                                 m, ntiles, tiles_per_row);
}

// round 8
// speedup vs baseline: 1.3169x; 1.1157x over previous
#include <cuda_runtime.h>

// Deriv2Matern52: out[i,a,j,b] = c^2 * ( (a==b)*A(i,j)*inv_l2[a] - 5*fr(i,j)*D[i,j,a]*D[i,j,b] )
// Champion configuration (measured 41.44us, DRAM-write roofline ~6.5TB/s):
//   phase 1: JT=256 threads compute per-(i,j) pair data into smem
//   phase 2: 512 threads map 1:1 onto output float4 half-rows
//            (thread t -> pair p=t/2, half=t&1); per a, one fully coalesced
//            512B-per-warp streaming store (st.global.cs.v4).

#define D_DIM 8
#define JT 256          // j-tile per block (phase1 threads)
#define NTHREADS 512    // = 2*JT (phase2 threads)
#define SSTRIDE 17      // smem row stride in floats (coprime with 32 banks)
#define SQRT5F 2.2360679774997896f

__global__ __launch_bounds__(NTHREADS) void deriv2_matern52_kernel(
    const float* __restrict__ X1,   // [n, 8]
    const float* __restrict__ X2,   // [m, 8]
    const float* __restrict__ cptr, // [1]
    const float* __restrict__ lptr, // [8]
    float* __restrict__ out,        // [n, 8, m, 8]
    int m)
{
    __shared__ float sp[JT * SSTRIDE];
    // sp[p*17 + 0..7]  = Dv[a]      (dx[a] * inv_l2[a])
    // sp[p*17 + 8]     = -5 * fr * c^2
    // sp[p*17 + 9..16] = A * c^2 * inv_l2[a]   (diagonal terms)

    const int t  = threadIdx.x;
    const int i  = blockIdx.y;
    const int j0 = blockIdx.x * JT;

    // ---------------- phase 1: pair data ----------------
    if (t < JT) {
        float invl2[D_DIM];
#pragma unroll
        for (int a = 0; a < D_DIM; a++) {
            float lv = __ldg(lptr + a);
            invl2[a] = 1.0f / (lv * lv);
        }
        float cv = __ldg(cptr);
        float c2 = cv * cv;

        const float4* x1p = reinterpret_cast<const float4*>(X1 + (size_t)i * D_DIM);
        const float4* x2p = reinterpret_cast<const float4*>(X2 + (size_t)(j0 + t) * D_DIM);
        float4 x1a = __ldg(x1p);
        float4 x1b = __ldg(x1p + 1);
        float4 x2a = __ldg(x2p);
        float4 x2b = __ldg(x2p + 1);

        float dx[D_DIM];
        dx[0] = x1a.x - x2a.x; dx[1] = x1a.y - x2a.y;
        dx[2] = x1a.z - x2a.z; dx[3] = x1a.w - x2a.w;
        dx[4] = x1b.x - x2b.x; dx[5] = x1b.y - x2b.y;
        dx[6] = x1b.z - x2b.z; dx[7] = x1b.w - x2b.w;

        float s = 0.0f;
        float* row = sp + t * SSTRIDE;
#pragma unroll
        for (int a = 0; a < D_DIM; a++) {
            float dv = dx[a] * invl2[a];
            row[a] = dv;
            s = fmaf(dx[a], dv, s);
        }
        float r   = sqrtf(s);
        float fr  = (5.0f / 3.0f) * expf(-SQRT5F * r);
        float A   = fr * fmaf(SQRT5F, r, 1.0f);
        float Ac2 = A * c2;
        row[8] = -5.0f * fr * c2;
#pragma unroll
        for (int a = 0; a < D_DIM; a++)
            row[9 + a] = Ac2 * invl2[a];
    }
    __syncthreads();

    // ---------------- phase 2: coalesced streaming stores ----------------
    // thread t -> pair p = t/2, half = t&1 (b in [half*4, half*4+4))
    const int p    = t >> 1;
    const int half = t & 1;
    const int hb   = half * 4;

    const float* row = sp + p * SSTRIDE;
    float Dv[D_DIM];
#pragma unroll
    for (int a = 0; a < D_DIM; a++)
        Dv[a] = row[a];
    const float m5 = row[8];
    float Ad[4];
#pragma unroll
    for (int x = 0; x < 4; x++)
        Ad[x] = row[9 + hb + x];

    // base element index of (i, a=0, j0+p, b=hb)
    float* dst = out + ((((size_t)i * D_DIM) * (size_t)m + (size_t)(j0 + p)) * D_DIM) + hb;
    const size_t astride = (size_t)m * D_DIM;

#pragma unroll
    for (int a = 0; a < D_DIM; a++) {
        float ta = m5 * Dv[a];
        float o0 = ta * Dv[hb + 0];
        float o1 = ta * Dv[hb + 1];
        float o2 = ta * Dv[hb + 2];
        float o3 = ta * Dv[hb + 3];
        if ((a >> 2) == half) {
            int x = a & 3;
            float add = Ad[x];
            if (x == 0) o0 += add;
            else if (x == 1) o1 += add;
            else if (x == 2) o2 += add;
            else o3 += add;
        }
        __stcs(reinterpret_cast<float4*>(dst + (size_t)a * astride),
               make_float4(o0, o1, o2, o3));
    }
}

extern "C" void kernel_launch(void* const* d_in, const int* in_sizes, int n_in,
                              void* d_out, int out_size)
{
    const float* X1 = (const float*)d_in[0];
    const float* X2 = (const float*)d_in[1];
    const float* c  = (const float*)d_in[2];
    const float* l  = (const float*)d_in[3];
    float* out = (float*)d_out;

    int n = in_sizes[0] / D_DIM;
    int m = in_sizes[1] / D_DIM;

    dim3 grid(m / JT, n);
    deriv2_matern52_kernel<<<grid, NTHREADS>>>(X1, X2, c, l, out, m);
}

// round 9
// speedup vs baseline: 1.3361x; 1.0146x over previous
#include <cuda_runtime.h>

// Deriv2Matern52: out[i,a,j,b] = c^2 * ( (a==b)*A(i,j)*inv_l2[a] - 5*fr(i,j)*D[i,j,a]*D[i,j,b] )
// FINAL / champion configuration (measured 41.4-42.3us across runs; at the
// GB300 DRAM-write roofline ~6.5TB/s for the mandatory 268MB output stream):
//   phase 1: JT=256 threads compute per-(i,j) pair data into smem
//   phase 2: 512 threads map 1:1 onto output float4 half-rows
//            (thread t -> pair p=t/2, half=t&1); per a, one fully coalesced
//            512B-per-warp streaming store (st.global.cs.v4).

#define D_DIM 8
#define JT 256          // j-tile per block (phase1 threads)
#define NTHREADS 512    // = 2*JT (phase2 threads)
#define SSTRIDE 17      // smem row stride in floats (coprime with 32 banks)
#define SQRT5F 2.2360679774997896f

__global__ __launch_bounds__(NTHREADS) void deriv2_matern52_kernel(
    const float* __restrict__ X1,   // [n, 8]
    const float* __restrict__ X2,   // [m, 8]
    const float* __restrict__ cptr, // [1]
    const float* __restrict__ lptr, // [8]
    float* __restrict__ out,        // [n, 8, m, 8]
    int m)
{
    __shared__ float sp[JT * SSTRIDE];
    // sp[p*17 + 0..7]  = Dv[a]      (dx[a] * inv_l2[a])
    // sp[p*17 + 8]     = -5 * fr * c^2
    // sp[p*17 + 9..16] = A * c^2 * inv_l2[a]   (diagonal terms)

    const int t  = threadIdx.x;
    const int i  = blockIdx.y;
    const int j0 = blockIdx.x * JT;

    // ---------------- phase 1: pair data ----------------
    if (t < JT) {
        float invl2[D_DIM];
#pragma unroll
        for (int a = 0; a < D_DIM; a++) {
            float lv = __ldg(lptr + a);
            invl2[a] = 1.0f / (lv * lv);
        }
        float cv = __ldg(cptr);
        float c2 = cv * cv;

        const float4* x1p = reinterpret_cast<const float4*>(X1 + (size_t)i * D_DIM);
        const float4* x2p = reinterpret_cast<const float4*>(X2 + (size_t)(j0 + t) * D_DIM);
        float4 x1a = __ldg(x1p);
        float4 x1b = __ldg(x1p + 1);
        float4 x2a = __ldg(x2p);
        float4 x2b = __ldg(x2p + 1);

        float dx[D_DIM];
        dx[0] = x1a.x - x2a.x; dx[1] = x1a.y - x2a.y;
        dx[2] = x1a.z - x2a.z; dx[3] = x1a.w - x2a.w;
        dx[4] = x1b.x - x2b.x; dx[5] = x1b.y - x2b.y;
        dx[6] = x1b.z - x2b.z; dx[7] = x1b.w - x2b.w;

        float s = 0.0f;
        float* row = sp + t * SSTRIDE;
#pragma unroll
        for (int a = 0; a < D_DIM; a++) {
            float dv = dx[a] * invl2[a];
            row[a] = dv;
            s = fmaf(dx[a], dv, s);
        }
        float r   = sqrtf(s);
        float fr  = (5.0f / 3.0f) * expf(-SQRT5F * r);
        float A   = fr * fmaf(SQRT5F, r, 1.0f);
        float Ac2 = A * c2;
        row[8] = -5.0f * fr * c2;
#pragma unroll
        for (int a = 0; a < D_DIM; a++)
            row[9 + a] = Ac2 * invl2[a];
    }
    __syncthreads();

    // ---------------- phase 2: coalesced streaming stores ----------------
    // thread t -> pair p = t/2, half = t&1 (b in [half*4, half*4+4))
    const int p    = t >> 1;
    const int half = t & 1;
    const int hb   = half * 4;

    const float* row = sp + p * SSTRIDE;
    float Dv[D_DIM];
#pragma unroll
    for (int a = 0; a < D_DIM; a++)
        Dv[a] = row[a];
    const float m5 = row[8];
    float Ad[4];
#pragma unroll
    for (int x = 0; x < 4; x++)
        Ad[x] = row[9 + hb + x];

    // base element index of (i, a=0, j0+p, b=hb)
    float* dst = out + ((((size_t)i * D_DIM) * (size_t)m + (size_t)(j0 + p)) * D_DIM) + hb;
    const size_t astride = (size_t)m * D_DIM;

#pragma unroll
    for (int a = 0; a < D_DIM; a++) {
        float ta = m5 * Dv[a];
        float o0 = ta * Dv[hb + 0];
        float o1 = ta * Dv[hb + 1];
        float o2 = ta * Dv[hb + 2];
        float o3 = ta * Dv[hb + 3];
        if ((a >> 2) == half) {
            int x = a & 3;
            float add = Ad[x];
            if (x == 0) o0 += add;
            else if (x == 1) o1 += add;
            else if (x == 2) o2 += add;
            else o3 += add;
        }
        __stcs(reinterpret_cast<float4*>(dst + (size_t)a * astride),
               make_float4(o0, o1, o2, o3));
    }
}

extern "C" void kernel_launch(void* const* d_in, const int* in_sizes, int n_in,
                              void* d_out, int out_size)
{
    const float* X1 = (const float*)d_in[0];
    const float* X2 = (const float*)d_in[1];
    const float* c  = (const float*)d_in[2];
    const float* l  = (const float*)d_in[3];
    float* out = (float*)d_out;

    int n = in_sizes[0] / D_DIM;
    int m = in_sizes[1] / D_DIM;

    dim3 grid(m / JT, n);
    deriv2_matern52_kernel<<<grid, NTHREADS>>>(X1, X2, c, l, out, m);
}